// round 14
// baseline (speedup 1.0000x reference)
#include <cuda_runtime.h>
#include <cuda_fp16.h>
#include <cstdint>

// Problem constants: B=4, L=4, N=2048, H=64, V=4, label_plus1=5
#define B_    4
#define L_    4
#define N_    2048
#define H_    64

// k_main pipeline: CTA tile 128m x 64e, k-tile 32, split-K=4 (one l per CTA)
#define STAGES      4
#define A_ROW       160                  // 128B content + 32B pad (conflict-free lds_v2)
#define B_ROW       80                   // 64B content + 16B pad (conflict-free lds_b32)
#define A_ST        (128 * A_ROW)        // 20480
#define B_ST        (64 * B_ROW)         // 5120
#define STAGE_BYTES (A_ST + B_ST)        // 25600
#define SMEM_MAIN   (STAGES * STAGE_BYTES)   // 102400

// Scratch (device globals; no allocation allowed)
__device__ __align__(128) __half d_gt[B_ * 4 * H_ * N_];   // [b,l,e,m] fp16

// ---------------------------------------------------------------------------
// Helpers
// ---------------------------------------------------------------------------
__device__ __forceinline__ uint32_t smem_u32(const void* p) {
    uint32_t a;
    asm("{ .reg .u64 t; cvta.to.shared.u64 t, %1; cvt.u32.u64 %0, t; }" : "=r"(a) : "l"(p));
    return a;
}
__device__ __forceinline__ void cpasync16(uint32_t saddr, const void* gaddr) {
    asm volatile("cp.async.cg.shared.global [%0], [%1], 16;" :: "r"(saddr), "l"(gaddr));
}
__device__ __forceinline__ void lds_v2(float& x, float& y, uint32_t a) {
    asm volatile("ld.shared.v2.f32 {%0, %1}, [%2];" : "=f"(x), "=f"(y) : "r"(a));
}
__device__ __forceinline__ uint32_t lds_b32(uint32_t a) {
    uint32_t v;
    asm volatile("ld.shared.b32 %0, [%1];" : "=r"(v) : "r"(a));
    return v;
}
__device__ __forceinline__ uint32_t cvt_h2(float hi, float lo) {   // pack {lo, hi}
    uint32_t r;
    asm("cvt.rn.f16x2.f32 %0, %1, %2;" : "=r"(r) : "f"(hi), "f"(lo));
    return r;
}
__device__ __forceinline__ void mma16816(float* c, const uint32_t* a, uint32_t b0, uint32_t b1) {
    asm volatile(
        "mma.sync.aligned.m16n8k16.row.col.f32.f16.f16.f32 "
        "{%0,%1,%2,%3}, {%4,%5,%6,%7}, {%8,%9}, {%0,%1,%2,%3};"
        : "+f"(c[0]), "+f"(c[1]), "+f"(c[2]), "+f"(c[3])
        : "r"(a[0]), "r"(a[1]), "r"(a[2]), "r"(a[3]), "r"(b0), "r"(b1));
}
__device__ __forceinline__ void red_add(float* p, float v) {
    asm volatile("red.global.add.f32 [%0], %1;" :: "l"(p), "f"(v) : "memory");
}
__device__ __forceinline__ float fast_tanh(float x) {
    float t = exp2f(x * 2.8853900817779268f);
    return 1.0f - __fdividef(2.0f, t + 1.0f);
}

// ---------------------------------------------------------------------------
// k_hg: per block (256 blocks, 32 rows each):
//   1) h = fast_tanh(LN(concat(x,feat)@fcw^T + fcb)) -> smem (warp-per-row)
//   2) for j = 0..4: M_j = (a_j@W)/5 in smem; g = h@M_j
//        j==0: out = x + g      j>=1: d_gt[b,j-1,e, mslice] = fp16(g^T)
// h -> g is row-local, so no inter-block sync is needed anywhere.
// ---------------------------------------------------------------------------
__global__ void __launch_bounds__(256, 2)
k_hg(const float* __restrict__ x, const float* __restrict__ feat,
     const float* __restrict__ fcw, const float* __restrict__ fcb,
     const float* __restrict__ lng, const float* __restrict__ lnb,
     const float* __restrict__ W, const float* __restrict__ a,
     float* __restrict__ out) {
    __shared__ float sw[64 * 67];        // fc weights, stride 67 (conflict-free)
    __shared__ float sp[192];            // fcb | lng | lnb
    __shared__ float srow[8][68];
    __shared__ float hs[32 * 68];        // h rows (local)
    __shared__ __align__(16) float Mj[64 * 68];   // M_j; reused as transpose buf

    int tid = threadIdx.x, warp = tid >> 5, lane = tid & 31;
    int row0 = blockIdx.x * 32;          // global row
    int b = row0 >> 11, nn0 = row0 & 2047;

    // ---- stage weights (two-phase batched: deep MLP) ----
    float wv[17];
#pragma unroll
    for (int i = 0; i < 17; i++) {
        int ii = tid + i * 256;
        wv[i] = (ii < 4224) ? fcw[ii] : 0.f;
    }
    float pv = (tid < 192) ? ((tid < 64) ? fcb[tid] :
                 (tid < 128) ? lng[tid - 64] : lnb[tid - 128]) : 0.f;
#pragma unroll
    for (int i = 0; i < 17; i++) {
        int ii = tid + i * 256;
        if (ii < 4224) sw[(ii / 66) * 67 + (ii % 66)] = wv[i];
    }
    if (tid < 192) sp[tid] = pv;
    __syncthreads();

    // ---- h: warp-per-row, 4 rows/warp, results to smem hs ----
#pragma unroll
    for (int it = 0; it < 4; it++) {
        int lrow = it * 8 + warp;
        int row = row0 + lrow;
        srow[warp][lane]      = x[(size_t)row * 64 + lane];
        srow[warp][lane + 32] = x[(size_t)row * 64 + lane + 32];
        if (lane < 2) srow[warp][64 + lane] = feat[(size_t)row * 2 + lane];
        __syncwarp();

        float h0a = sp[lane], h0b = 0.f;
        float h1a = sp[lane + 32], h1b = 0.f;
#pragma unroll
        for (int k = 0; k < 66; k += 2) {
            float xk0 = srow[warp][k], xk1 = srow[warp][k + 1];
            h0a += sw[lane * 67 + k] * xk0;
            h0b += sw[lane * 67 + k + 1] * xk1;
            h1a += sw[(lane + 32) * 67 + k] * xk0;
            h1b += sw[(lane + 32) * 67 + k + 1] * xk1;
        }
        float h0 = h0a + h0b, h1 = h1a + h1b;
        float s = h0 + h1, sq = h0 * h0 + h1 * h1;
#pragma unroll
        for (int o = 16; o > 0; o >>= 1) {
            s  += __shfl_xor_sync(0xffffffff, s,  o);
            sq += __shfl_xor_sync(0xffffffff, sq, o);
        }
        float mu  = s * (1.f / 64.f);
        float var = sq * (1.f / 64.f) - mu * mu;
        float inv = rsqrtf(var + 1e-5f);
        hs[lrow * 68 + lane]      = fast_tanh((h0 - mu) * inv * sp[64 + lane]      + sp[128 + lane]);
        hs[lrow * 68 + lane + 32] = fast_tanh((h1 - mu) * inv * sp[64 + lane + 32] + sp[128 + lane + 32]);
        __syncwarp();
    }

    // ---- g_j = h @ M_j for j = 0..4 ----
    int r = tid >> 3, cg = (tid & 7) * 8;     // 32 rows x 8 cols/thread
#pragma unroll 1
    for (int j = 0; j < 5; j++) {
        __syncthreads();                       // Mj/tb reuse boundary
        // build M_j (batched gather: 16 indep 4-load bundles in flight)
        float mv[16];
        {
            float a0 = a[j * 4 + 0], a1 = a[j * 4 + 1],
                  a2 = a[j * 4 + 2], a3 = a[j * 4 + 3];
#pragma unroll
            for (int i = 0; i < 16; i++) {
                int idx = tid + i * 256;
                int d = idx >> 6, e = idx & 63;
                const float* wp = W + (size_t)(d * 4) * 64 + e;
                mv[i] = (a0 * wp[0] + a1 * wp[64] + a2 * wp[128] + a3 * wp[192]) * 0.2f;
            }
        }
#pragma unroll
        for (int i = 0; i < 16; i++) {
            int idx = tid + i * 256;
            Mj[(idx >> 6) * 68 + (idx & 63)] = mv[i];
        }
        __syncthreads();

        float acc[8];
#pragma unroll
        for (int c = 0; c < 8; c++) acc[c] = 0.f;
#pragma unroll 8
        for (int d = 0; d < 64; d++) {
            float hv = hs[r * 68 + d];                         // broadcast in group
            float4 m0 = *(const float4*)&Mj[d * 68 + cg];
            float4 m1 = *(const float4*)&Mj[d * 68 + cg + 4];
            acc[0] += hv * m0.x; acc[1] += hv * m0.y;
            acc[2] += hv * m0.z; acc[3] += hv * m0.w;
            acc[4] += hv * m1.x; acc[5] += hv * m1.y;
            acc[6] += hv * m1.z; acc[7] += hv * m1.w;
        }

        if (j == 0) {
            const float* xp = x   + ((size_t)row0 + r) * 64 + cg;
            float*       op = out + ((size_t)row0 + r) * 64 + cg;
            float4 x0 = *(const float4*)xp, x1 = *(const float4*)(xp + 4);
            float4 o0, o1;
            o0.x = acc[0] + x0.x; o0.y = acc[1] + x0.y;
            o0.z = acc[2] + x0.z; o0.w = acc[3] + x0.w;
            o1.x = acc[4] + x1.x; o1.y = acc[5] + x1.y;
            o1.z = acc[6] + x1.z; o1.w = acc[7] + x1.w;
            *(float4*)op = o0; *(float4*)(op + 4) = o1;
        } else {
            __syncthreads();                   // done reading Mj -> reuse as tb
            float* tb = Mj;                    // tb[e][r], stride 33
#pragma unroll
            for (int c = 0; c < 8; c++) tb[(cg + c) * 33 + r] = acc[c];
            __syncthreads();
            int e = tid >> 2, mq = (tid & 3) * 8;
            __half2 h2[4];
#pragma unroll
            for (int q = 0; q < 4; q++)
                h2[q] = __floats2half2_rn(tb[e * 33 + mq + 2 * q],
                                          tb[e * 33 + mq + 2 * q + 1]);
            __half* dst = d_gt + ((size_t)(b * 4 + j - 1) * 64 + e) * 2048 + nn0 + mq;
            *(uint4*)dst = *(uint4*)&h2[0];
        }
    }
}

// ---------------------------------------------------------------------------
// k_main (unchanged, best measured): out += sum_m adj[b,l,n,m] * g_{l+1}[b,m,:]
// Grid (16 m-tiles, 4 b, 4 l) = 256 CTAs, 2/SM. 4-stage cp.async, fp16 MMA.
// ---------------------------------------------------------------------------
__device__ __forceinline__ void issue_stage(int t, uint32_t sb, int tid,
                                            const float* __restrict__ adjl,
                                            const __half* __restrict__ gtl, int n0) {
    if (t < 64) {
        int slot = t & (STAGES - 1);
        int m0 = t << 5;
        uint32_t aB = sb + slot * STAGE_BYTES;
        uint32_t bB = aB + A_ST;
#pragma unroll
        for (int i = 0; i < 4; i++) {
            int ch = tid + i * 256;
            int row = ch >> 3, c16 = ch & 7;
            cpasync16(aB + row * A_ROW + c16 * 16,
                      adjl + ((size_t)(n0 + row)) * N_ + m0 + c16 * 4);
        }
        {
            int row = tid >> 2, c16 = tid & 3;
            cpasync16(bB + row * B_ROW + c16 * 16,
                      gtl + (size_t)row * 2048 + m0 + c16 * 8);
        }
    }
    asm volatile("cp.async.commit_group;");
}

__global__ void __launch_bounds__(256, 2)
k_main(const float* __restrict__ adj, float* __restrict__ out) {
    extern __shared__ __align__(128) char smem[];
    uint32_t sb = smem_u32(smem);
    int tid = threadIdx.x, wid = tid >> 5, lane = tid & 31;
    int gid = lane >> 2, tig = lane & 3;
    int b = blockIdx.y;
    int n0 = blockIdx.x * 128;
    int l = blockIdx.z;
    int warp_m = wid & 3, warp_n = wid >> 2;

    const float*  adjl = adj  + ((size_t)b * L_ + l) * N_ * N_;
    const __half* gtl  = d_gt + (size_t)(b * 4 + l) * 64 * 2048;

    uint32_t ar_rel = (uint32_t)(warp_m * 32 + gid) * A_ROW + tig * 8;
    uint32_t bn_rel[4];
#pragma unroll
    for (int nt = 0; nt < 4; nt++)
        bn_rel[nt] = A_ST + (uint32_t)(warp_n * 32 + nt * 8 + gid) * B_ROW + tig * 4;

    float acc[2][4][4];
#pragma unroll
    for (int mt = 0; mt < 2; mt++)
#pragma unroll
        for (int nt = 0; nt < 4; nt++)
#pragma unroll
            for (int q = 0; q < 4; q++) acc[mt][nt][q] = 0.f;

#pragma unroll
    for (int s = 0; s < STAGES - 1; s++) issue_stage(s, sb, tid, adjl, gtl, n0);

#pragma unroll 1
    for (int t = 0; t < 64; t++) {
        asm volatile("cp.async.wait_group %0;" :: "n"(STAGES - 2));
        __syncthreads();
        issue_stage(t + STAGES - 1, sb, tid, adjl, gtl, n0);

        uint32_t base = sb + (t & (STAGES - 1)) * STAGE_BYTES;
        uint32_t ar = base + ar_rel;
#pragma unroll
        for (int ks = 0; ks < 2; ks++) {
            uint32_t afr[2][4];
#pragma unroll
            for (int mt = 0; mt < 2; mt++)
#pragma unroll
                for (int kk = 0; kk < 2; kk++) {
                    float x0, x1, y0, y1;
                    uint32_t ad = ar + mt * (16 * A_ROW) + ks * 64 + kk * 32;
                    lds_v2(x0, x1, ad);
                    lds_v2(y0, y1, ad + 8 * A_ROW);
                    afr[mt][kk * 2 + 0] = cvt_h2(x1, x0);
                    afr[mt][kk * 2 + 1] = cvt_h2(y1, y0);
                }
#pragma unroll
            for (int nt = 0; nt < 4; nt++) {
                uint32_t b0 = lds_b32(base + bn_rel[nt] + ks * 32);
                uint32_t b1 = lds_b32(base + bn_rel[nt] + ks * 32 + 16);
                mma16816(acc[0][nt], afr[0], b0, b1);
                mma16816(acc[1][nt], afr[1], b0, b1);
            }
        }
    }

#pragma unroll
    for (int mt = 0; mt < 2; mt++)
#pragma unroll
    for (int h = 0; h < 2; h++) {
        int node = n0 + warp_m * 32 + mt * 16 + gid + 8 * h;
        float* basep = out + ((size_t)b * N_ + node) * 64;
#pragma unroll
        for (int nt = 0; nt < 4; nt++) {
            int col = warp_n * 32 + nt * 8 + 2 * tig;
            red_add(basep + col,     acc[mt][nt][h * 2 + 0]);
            red_add(basep + col + 1, acc[mt][nt][h * 2 + 1]);
        }
    }
}

// ---------------------------------------------------------------------------
// Launch: x, feature, adj, fc_w, fc_b, ln_g, ln_b, W, a
// ---------------------------------------------------------------------------
extern "C" void kernel_launch(void* const* d_in, const int* in_sizes, int n_in,
                              void* d_out, int out_size) {
    const float* x    = (const float*)d_in[0];
    const float* feat = (const float*)d_in[1];
    const float* adj  = (const float*)d_in[2];
    const float* fcw  = (const float*)d_in[3];
    const float* fcb  = (const float*)d_in[4];
    const float* lng  = (const float*)d_in[5];
    const float* lnb  = (const float*)d_in[6];
    const float* W    = (const float*)d_in[7];
    const float* a    = (const float*)d_in[8];
    float* out = (float*)d_out;

    cudaFuncSetAttribute(k_main, cudaFuncAttributeMaxDynamicSharedMemorySize, SMEM_MAIN);

    k_hg<<<256, 256>>>(x, feat, fcw, fcb, lng, lnb, W, a, out);
    k_main<<<dim3(16, 4, 4), 256, SMEM_MAIN>>>(adj, out);
}

// round 15
// speedup vs baseline: 1.1959x; 1.1959x over previous
#include <cuda_runtime.h>
#include <cuda_fp16.h>
#include <cstdint>

// Problem constants: B=4, L=4, N=2048, H=64, V=4, label_plus1=5
#define B_    4
#define L_    4
#define N_    2048
#define H_    64

// k_main pipeline: CTA tile 128m x 64e, k-tile 32, split-K=4 (one l per CTA)
#define STAGES      4
#define A_ROW       160                  // 128B content + 32B pad (conflict-free lds_v2)
#define B_ROW       80                   // 64B content + 16B pad (conflict-free lds_b32)
#define A_ST        (128 * A_ROW)        // 20480
#define B_ST        (64 * B_ROW)         // 5120
#define STAGE_BYTES (A_ST + B_ST)        // 25600
#define SMEM_MAIN   (STAGES * STAGE_BYTES)   // 102400

// Scratch (device globals; no allocation allowed)
__device__ __align__(128) float  d_h [B_ * N_ * H_];       // tanh(LN(fc)) fp32
__device__ __align__(128) __half d_gt[B_ * 4 * H_ * N_];   // [b,l,e,m] fp16

// ---------------------------------------------------------------------------
// Helpers
// ---------------------------------------------------------------------------
__device__ __forceinline__ uint32_t smem_u32(const void* p) {
    uint32_t a;
    asm("{ .reg .u64 t; cvta.to.shared.u64 t, %1; cvt.u32.u64 %0, t; }" : "=r"(a) : "l"(p));
    return a;
}
__device__ __forceinline__ void cpasync16(uint32_t saddr, const void* gaddr) {
    asm volatile("cp.async.cg.shared.global [%0], [%1], 16;" :: "r"(saddr), "l"(gaddr));
}
__device__ __forceinline__ void lds_v2(float& x, float& y, uint32_t a) {
    asm volatile("ld.shared.v2.f32 {%0, %1}, [%2];" : "=f"(x), "=f"(y) : "r"(a));
}
__device__ __forceinline__ uint32_t lds_b32(uint32_t a) {
    uint32_t v;
    asm volatile("ld.shared.b32 %0, [%1];" : "=r"(v) : "r"(a));
    return v;
}
__device__ __forceinline__ uint32_t cvt_h2(float hi, float lo) {   // pack {lo, hi}
    uint32_t r;
    asm("cvt.rn.f16x2.f32 %0, %1, %2;" : "=r"(r) : "f"(hi), "f"(lo));
    return r;
}
__device__ __forceinline__ void mma16816(float* c, const uint32_t* a, uint32_t b0, uint32_t b1) {
    asm volatile(
        "mma.sync.aligned.m16n8k16.row.col.f32.f16.f16.f32 "
        "{%0,%1,%2,%3}, {%4,%5,%6,%7}, {%8,%9}, {%0,%1,%2,%3};"
        : "+f"(c[0]), "+f"(c[1]), "+f"(c[2]), "+f"(c[3])
        : "r"(a[0]), "r"(a[1]), "r"(a[2]), "r"(a[3]), "r"(b0), "r"(b1));
}
__device__ __forceinline__ void red_add(float* p, float v) {
    asm volatile("red.global.add.f32 [%0], %1;" :: "l"(p), "f"(v) : "memory");
}
__device__ __forceinline__ float fast_tanh(float x) {
    float t = exp2f(x * 2.8853900817779268f);
    return 1.0f - __fdividef(2.0f, t + 1.0f);
}

// ---------------------------------------------------------------------------
// k_h: h = fast_tanh(LayerNorm(concat(x,feat) @ fc_w^T + fc_b))
// 512 blocks x 256 threads; warp-per-row, 2 rows/warp (short serial tail,
// ~3.5 blocks/SM to hide weight staging). Two-phase batched weight load.
// ---------------------------------------------------------------------------
__global__ void k_h(const float* __restrict__ x, const float* __restrict__ feat,
                    const float* __restrict__ fcw, const float* __restrict__ fcb,
                    const float* __restrict__ lng, const float* __restrict__ lnb) {
    __shared__ float sw[64 * 67];
    __shared__ float sp[3][64];
    __shared__ float srow[8][68];
    int tid = threadIdx.x;

    // phase 1: gather weights to registers (independent loads, deep MLP)
    float wv[17];
#pragma unroll
    for (int i = 0; i < 17; i++) {
        int ii = tid + i * 256;
        wv[i] = (ii < 4224) ? fcw[ii] : 0.f;
    }
    float pv = (tid < 192) ? ((tid < 64) ? fcb[tid] :
                 (tid < 128) ? lng[tid - 64] : lnb[tid - 128]) : 0.f;
    // phase 2: store to smem (stride 67 -> conflict-free row reads)
#pragma unroll
    for (int i = 0; i < 17; i++) {
        int ii = tid + i * 256;
        if (ii < 4224) sw[(ii / 66) * 67 + (ii % 66)] = wv[i];
    }
    if (tid < 192) sp[tid >> 6][tid & 63] = pv;
    int warp = tid >> 5, lane = tid & 31;
    __syncthreads();

#pragma unroll
    for (int it = 0; it < 2; it++) {
        int row = blockIdx.x * 16 + it * 8 + warp;
        srow[warp][lane]      = x[(size_t)row * 64 + lane];
        srow[warp][lane + 32] = x[(size_t)row * 64 + lane + 32];
        if (lane < 2) srow[warp][64 + lane] = feat[(size_t)row * 2 + lane];
        __syncwarp();

        // dual accumulators: halve the serial FMA chain
        float h0a = sp[0][lane], h0b = 0.f;
        float h1a = sp[0][lane + 32], h1b = 0.f;
#pragma unroll
        for (int k = 0; k < 66; k += 2) {
            float xk0 = srow[warp][k], xk1 = srow[warp][k + 1];
            h0a += sw[lane * 67 + k] * xk0;
            h0b += sw[lane * 67 + k + 1] * xk1;
            h1a += sw[(lane + 32) * 67 + k] * xk0;
            h1b += sw[(lane + 32) * 67 + k + 1] * xk1;
        }
        float h0 = h0a + h0b, h1 = h1a + h1b;
        float s = h0 + h1, sq = h0 * h0 + h1 * h1;
#pragma unroll
        for (int o = 16; o > 0; o >>= 1) {
            s  += __shfl_xor_sync(0xffffffff, s,  o);
            sq += __shfl_xor_sync(0xffffffff, sq, o);
        }
        float mu  = s * (1.f / 64.f);
        float var = sq * (1.f / 64.f) - mu * mu;
        float inv = rsqrtf(var + 1e-5f);
        h0 = fast_tanh((h0 - mu) * inv * sp[1][lane]      + sp[2][lane]);
        h1 = fast_tanh((h1 - mu) * inv * sp[1][lane + 32] + sp[2][lane + 32]);
        d_h[(size_t)row * 64 + lane]      = h0;
        d_h[(size_t)row * 64 + lane + 32] = h1;
        __syncwarp();
    }
}

// ---------------------------------------------------------------------------
// k_g: M_j = (a_j @ W)/5 in-block, then g_j = h @ M_j.
// Grid (128 row-tiles, 5 j). j=0 -> out = x + g0; j>=1 -> d_gt fp16 transposed.
// Two-phase batched gather; float4 conflict-free operand reads.
// ---------------------------------------------------------------------------
__global__ void k_g(const float* __restrict__ W, const float* __restrict__ a,
                    const float* __restrict__ x, float* __restrict__ out) {
    __shared__ __align__(16) float Ms[64][68];   // M_j; later transpose buffer
    __shared__ float hs[64][65];
    int tid = threadIdx.x;
    int j = blockIdx.y;
    int row0 = blockIdx.x * 64;
    int b = row0 >> 11, nn0 = row0 & 2047;
    float a0 = a[j * 4 + 0], a1 = a[j * 4 + 1], a2 = a[j * 4 + 2], a3 = a[j * 4 + 3];

    // phase 1: gather (independent loads, deep MLP)
    float hv[16], mv[16];
#pragma unroll
    for (int i = 0; i < 16; i++) {
        int idx = tid + i * 256;                 // 0..4095
        hv[i] = d_h[(size_t)row0 * 64 + idx];
        int d = idx >> 6, e = idx & 63;
        const float* wp = W + (size_t)(d * 4) * 64 + e;
        mv[i] = (a0 * wp[0] + a1 * wp[64] + a2 * wp[128] + a3 * wp[192]) * 0.2f;
    }
    // phase 2: store to smem
#pragma unroll
    for (int i = 0; i < 16; i++) {
        int idx = tid + i * 256;
        hs[idx >> 6][idx & 63] = hv[i];
        Ms[idx >> 6][idx & 63] = mv[i];
    }
    __syncthreads();

    int r = tid >> 2, tig = tid & 3;
    float acc[16];                               // [q][i]
#pragma unroll
    for (int c = 0; c < 16; c++) acc[c] = 0.f;
#pragma unroll 8
    for (int d = 0; d < 64; d++) {
        float hvb = hs[r][d];
#pragma unroll
        for (int q = 0; q < 4; q++) {
            float4 m = *(const float4*)&Ms[d][tig * 4 + 16 * q];
            acc[4 * q + 0] += hvb * m.x;
            acc[4 * q + 1] += hvb * m.y;
            acc[4 * q + 2] += hvb * m.z;
            acc[4 * q + 3] += hvb * m.w;
        }
    }
    if (j == 0) {
        const float4* xp = (const float4*)(x   + ((size_t)row0 + r) * 64);
        float4*       op = (float4*)(out + ((size_t)row0 + r) * 64);
#pragma unroll
        for (int q = 0; q < 4; q++) {
            float4 xv = xp[tig + 4 * q], o;
            o.x = acc[4 * q + 0] + xv.x;
            o.y = acc[4 * q + 1] + xv.y;
            o.z = acc[4 * q + 2] + xv.z;
            o.w = acc[4 * q + 3] + xv.w;
            op[tig + 4 * q] = o;
        }
    } else {
        __syncthreads();                          // everyone done reading Ms
        float* tb = &Ms[0][0];                    // reuse as transpose buffer
#pragma unroll
        for (int q = 0; q < 4; q++)
#pragma unroll
            for (int i = 0; i < 4; i++)
                tb[(tig * 4 + 16 * q + i) * 68 + r] = acc[4 * q + i];
        __syncthreads();
        int e = tid >> 2, ms = (tid & 3) * 16;
        __half2 h2[8];
#pragma unroll
        for (int q = 0; q < 8; q++)
            h2[q] = __floats2half2_rn(tb[e * 68 + ms + 2 * q], tb[e * 68 + ms + 2 * q + 1]);
        __half* dst = d_gt + ((size_t)(b * 4 + j - 1) * 64 + e) * 2048 + nn0 + ms;
        uint4* d4 = (uint4*)dst;
        d4[0] = *(uint4*)&h2[0];
        d4[1] = *(uint4*)&h2[4];
    }
}

// ---------------------------------------------------------------------------
// k_main (unchanged, best measured): out += sum_m adj[b,l,n,m] * g_{l+1}[b,m,:]
// Grid (16 m-tiles, 4 b, 4 l) = 256 CTAs, 2/SM. 4-stage cp.async, fp16 MMA.
// ---------------------------------------------------------------------------
__device__ __forceinline__ void issue_stage(int t, uint32_t sb, int tid,
                                            const float* __restrict__ adjl,
                                            const __half* __restrict__ gtl, int n0) {
    if (t < 64) {
        int slot = t & (STAGES - 1);
        int m0 = t << 5;
        uint32_t aB = sb + slot * STAGE_BYTES;
        uint32_t bB = aB + A_ST;
#pragma unroll
        for (int i = 0; i < 4; i++) {
            int ch = tid + i * 256;
            int row = ch >> 3, c16 = ch & 7;
            cpasync16(aB + row * A_ROW + c16 * 16,
                      adjl + ((size_t)(n0 + row)) * N_ + m0 + c16 * 4);
        }
        {
            int row = tid >> 2, c16 = tid & 3;
            cpasync16(bB + row * B_ROW + c16 * 16,
                      gtl + (size_t)row * 2048 + m0 + c16 * 8);
        }
    }
    asm volatile("cp.async.commit_group;");
}

__global__ void __launch_bounds__(256, 2)
k_main(const float* __restrict__ adj, float* __restrict__ out) {
    extern __shared__ __align__(128) char smem[];
    uint32_t sb = smem_u32(smem);
    int tid = threadIdx.x, wid = tid >> 5, lane = tid & 31;
    int gid = lane >> 2, tig = lane & 3;
    int b = blockIdx.y;
    int n0 = blockIdx.x * 128;
    int l = blockIdx.z;
    int warp_m = wid & 3, warp_n = wid >> 2;

    const float*  adjl = adj  + ((size_t)b * L_ + l) * N_ * N_;
    const __half* gtl  = d_gt + (size_t)(b * 4 + l) * 64 * 2048;

    uint32_t ar_rel = (uint32_t)(warp_m * 32 + gid) * A_ROW + tig * 8;
    uint32_t bn_rel[4];
#pragma unroll
    for (int nt = 0; nt < 4; nt++)
        bn_rel[nt] = A_ST + (uint32_t)(warp_n * 32 + nt * 8 + gid) * B_ROW + tig * 4;

    float acc[2][4][4];
#pragma unroll
    for (int mt = 0; mt < 2; mt++)
#pragma unroll
        for (int nt = 0; nt < 4; nt++)
#pragma unroll
            for (int q = 0; q < 4; q++) acc[mt][nt][q] = 0.f;

#pragma unroll
    for (int s = 0; s < STAGES - 1; s++) issue_stage(s, sb, tid, adjl, gtl, n0);

#pragma unroll 1
    for (int t = 0; t < 64; t++) {
        asm volatile("cp.async.wait_group %0;" :: "n"(STAGES - 2));
        __syncthreads();
        issue_stage(t + STAGES - 1, sb, tid, adjl, gtl, n0);

        uint32_t base = sb + (t & (STAGES - 1)) * STAGE_BYTES;
        uint32_t ar = base + ar_rel;
#pragma unroll
        for (int ks = 0; ks < 2; ks++) {
            uint32_t afr[2][4];
#pragma unroll
            for (int mt = 0; mt < 2; mt++)
#pragma unroll
                for (int kk = 0; kk < 2; kk++) {
                    float x0, x1, y0, y1;
                    uint32_t ad = ar + mt * (16 * A_ROW) + ks * 64 + kk * 32;
                    lds_v2(x0, x1, ad);
                    lds_v2(y0, y1, ad + 8 * A_ROW);
                    afr[mt][kk * 2 + 0] = cvt_h2(x1, x0);
                    afr[mt][kk * 2 + 1] = cvt_h2(y1, y0);
                }
#pragma unroll
            for (int nt = 0; nt < 4; nt++) {
                uint32_t b0 = lds_b32(base + bn_rel[nt] + ks * 32);
                uint32_t b1 = lds_b32(base + bn_rel[nt] + ks * 32 + 16);
                mma16816(acc[0][nt], afr[0], b0, b1);
                mma16816(acc[1][nt], afr[1], b0, b1);
            }
        }
    }

#pragma unroll
    for (int mt = 0; mt < 2; mt++)
#pragma unroll
    for (int h = 0; h < 2; h++) {
        int node = n0 + warp_m * 32 + mt * 16 + gid + 8 * h;
        float* basep = out + ((size_t)b * N_ + node) * 64;
#pragma unroll
        for (int nt = 0; nt < 4; nt++) {
            int col = warp_n * 32 + nt * 8 + 2 * tig;
            red_add(basep + col,     acc[mt][nt][h * 2 + 0]);
            red_add(basep + col + 1, acc[mt][nt][h * 2 + 1]);
        }
    }
}

// ---------------------------------------------------------------------------
// Launch: x, feature, adj, fc_w, fc_b, ln_g, ln_b, W, a
// ---------------------------------------------------------------------------
extern "C" void kernel_launch(void* const* d_in, const int* in_sizes, int n_in,
                              void* d_out, int out_size) {
    const float* x    = (const float*)d_in[0];
    const float* feat = (const float*)d_in[1];
    const float* adj  = (const float*)d_in[2];
    const float* fcw  = (const float*)d_in[3];
    const float* fcb  = (const float*)d_in[4];
    const float* lng  = (const float*)d_in[5];
    const float* lnb  = (const float*)d_in[6];
    const float* W    = (const float*)d_in[7];
    const float* a    = (const float*)d_in[8];
    float* out = (float*)d_out;

    cudaFuncSetAttribute(k_main, cudaFuncAttributeMaxDynamicSharedMemorySize, SMEM_MAIN);

    k_h<<<512, 256>>>(x, feat, fcw, fcb, lng, lnb);
    k_g<<<dim3(128, 5), 256>>>(W, a, x, out);
    k_main<<<dim3(16, 4, 4), 256, SMEM_MAIN>>>(adj, out);
}